// round 4
// baseline (speedup 1.0000x reference)
#include <cuda_runtime.h>

// CausalConv1d: x (4, 2048, 8192) f32, depthwise weight (2048, 1, 16), bias (2048)
// out[n,c,l] = sum_{k=0..15} x[n,c,l-15+k] * w[c,0,k] + bias[c]   (zero-pad left)
//
// L1-port-minimal scheme: each thread loads ONLY its own vec4 (coalesced,
// 4 wavefronts/warp) and gets the 16-float left halo from neighbor lanes via
// __shfl_up_sync (shuffle crossbar, not the l1tex data port). Lanes 0-3 fill
// their out-of-warp halo with small predicated global loads (zero at row edge).

#define DIM   2048
#define LEN   8192
#define KSZ   16
#define BLOCK 256
#define OPT   4
#define TILE  (BLOCK * OPT)          // 1024
#define TILES_PER_ROW (LEN / TILE)   // 8

__global__ __launch_bounds__(BLOCK) void causal_conv1d_kernel(
    const float* __restrict__ x,
    const float* __restrict__ w,
    const float* __restrict__ bias,
    float* __restrict__ out)
{
    const int tid  = threadIdx.x;
    const int lane = tid & 31;
    const int row  = blockIdx.x >> 3;                 // / TILES_PER_ROW
    const int tile = blockIdx.x & (TILES_PER_ROW - 1);
    const int ch   = row & (DIM - 1);                 // row = n*DIM + c

    const float* __restrict__ xrow = x   + (size_t)row * LEN;
    float*       __restrict__ orow = out + (size_t)row * LEN;

    const int base = tile * TILE + OPT * tid;         // first output index (mult of 4)

    // ---- own vec4: x[base .. base+3]  (always in range) ----
    float4 v = *reinterpret_cast<const float4*>(xrow + base);

    // ---- edge fallback loads for lanes 0..3 (their shfl_up source is out of warp) ----
    // g[d-1] = x[base-4d .. base-4d+3], needed by lane < d; zero-fill past row start.
    float4 g[4];
    #pragma unroll
    for (int d = 1; d <= 4; d++) {
        g[d - 1] = make_float4(0.f, 0.f, 0.f, 0.f);
        if (lane < d) {
            const int m = base - 4 * d;
            if (m >= 0) g[d - 1] = *reinterpret_cast<const float4*>(xrow + m);
        }
    }

    // ---- halo via shuffle: h[d-1] = lane (t-d)'s v = x[base-4d .. base-4d+3] ----
    float4 h[4];
    #pragma unroll
    for (int d = 1; d <= 4; d++) {
        float4 s;
        s.x = __shfl_up_sync(0xffffffffu, v.x, d);
        s.y = __shfl_up_sync(0xffffffffu, v.y, d);
        s.z = __shfl_up_sync(0xffffffffu, v.z, d);
        s.w = __shfl_up_sync(0xffffffffu, v.w, d);
        h[d - 1] = (lane >= d) ? s : g[d - 1];
    }

    // ---- assemble window r[i] = x[base-16+i], i in [0,20) ----
    float r[OPT + KSZ];
    r[0]  = h[3].x; r[1]  = h[3].y; r[2]  = h[3].z; r[3]  = h[3].w;
    r[4]  = h[2].x; r[5]  = h[2].y; r[6]  = h[2].z; r[7]  = h[2].w;
    r[8]  = h[1].x; r[9]  = h[1].y; r[10] = h[1].z; r[11] = h[1].w;
    r[12] = h[0].x; r[13] = h[0].y; r[14] = h[0].z; r[15] = h[0].w;
    r[16] = v.x;    r[17] = v.y;    r[18] = v.z;    r[19] = v.w;

    // ---- weights: 4 warp-uniform vec4 loads (L1 broadcast), bias scalar ----
    float wr[KSZ];
    const float4* w4 = reinterpret_cast<const float4*>(w + ch * KSZ);
    #pragma unroll
    for (int q = 0; q < 4; q++) {
        float4 t = w4[q];
        wr[4 * q + 0] = t.x; wr[4 * q + 1] = t.y;
        wr[4 * q + 2] = t.z; wr[4 * q + 3] = t.w;
    }
    const float b = bias[ch];

    // ---- compute: out[base+m] = b + sum_k wr[k] * r[m+1+k] ----
    float acc[OPT];
    #pragma unroll
    for (int m = 0; m < OPT; m++) {
        float a = b;
        #pragma unroll
        for (int k = 0; k < KSZ; k++) a = fmaf(wr[k], r[m + 1 + k], a);
        acc[m] = a;
    }

    float4 o; o.x = acc[0]; o.y = acc[1]; o.z = acc[2]; o.w = acc[3];
    *reinterpret_cast<float4*>(orow + base) = o;
}

extern "C" void kernel_launch(void* const* d_in, const int* in_sizes, int n_in,
                              void* d_out, int out_size)
{
    const float* x    = (const float*)d_in[0];
    const float* w    = (const float*)d_in[1];
    const float* bias = (const float*)d_in[2];
    float* out        = (float*)d_out;

    const int rows = 4 * DIM;                          // 8192
    const int blocks = rows * TILES_PER_ROW;           // 65536
    causal_conv1d_kernel<<<blocks, BLOCK>>>(x, w, bias, out);
}

// round 5
// speedup vs baseline: 1.3420x; 1.3420x over previous
#include <cuda_runtime.h>

// CausalConv1d: x (4, 2048, 8192) f32, depthwise weight (2048, 1, 16), bias (2048)
// out[n,c,l] = sum_{k=0..15} x[n,c,l-15+k] * w[c,0,k] + bias[c]   (zero-pad left)
//
// R2 access pattern (contiguous 16B lane stride, 5 overlapping coalesced
// LDG.128 per 4 outputs) but J=4 tiles per thread on the same row:
// weights/bias loaded once per thread, edge guard paid only on tile 0.
// Memory instructions per 512B of output drop 11 -> 6.25 (LSU-issue bound).

#define DIM   2048
#define LEN   8192
#define KSZ   16
#define BLOCK 256
#define OPT   4
#define JT    4                       // tiles per thread
#define TILE  (BLOCK * OPT)           // 1024
#define SPAN  (TILE * JT)             // 4096 outputs per block
#define HALVES_PER_ROW (LEN / SPAN)   // 2

__global__ __launch_bounds__(BLOCK, 4) void causal_conv1d_kernel(
    const float* __restrict__ x,
    const float* __restrict__ w,
    const float* __restrict__ bias,
    float* __restrict__ out)
{
    const int tid  = threadIdx.x;
    const int row  = blockIdx.x >> 1;                 // / HALVES_PER_ROW
    const int half = blockIdx.x & 1;
    const int ch   = row & (DIM - 1);                 // row = n*DIM + c

    const float* __restrict__ xrow = x   + (size_t)row * LEN;
    float*       __restrict__ orow = out + (size_t)row * LEN;

    // ---- weights + bias once per thread (warp-uniform vec4 loads) ----
    float wr[KSZ];
    const float4* w4 = reinterpret_cast<const float4*>(w + ch * KSZ);
    #pragma unroll
    for (int q = 0; q < 4; q++) {
        float4 t = w4[q];
        wr[4 * q + 0] = t.x; wr[4 * q + 1] = t.y;
        wr[4 * q + 2] = t.z; wr[4 * q + 3] = t.w;
    }
    const float b = bias[ch];

    const int base0 = half * SPAN + OPT * tid;        // first tile's output base

    #pragma unroll
    for (int j = 0; j < JT; j++) {
        const int base = base0 + j * TILE;

        // window r[i] = xrow[base - 16 + i], i in [0,20): 5 coalesced vec4 loads.
        // Underflow (m<0) only possible on the very first tile of the row.
        float r[OPT + KSZ];
        #pragma unroll
        for (int q = 0; q < 5; q++) {
            const int m = base - 16 + 4 * q;
            float4 v;
            if (j == 0) {                              // compile-time branch
                v = make_float4(0.f, 0.f, 0.f, 0.f);
                if (m >= 0) v = *reinterpret_cast<const float4*>(xrow + m);
            } else {
                v = *reinterpret_cast<const float4*>(xrow + m);
            }
            r[4 * q + 0] = v.x; r[4 * q + 1] = v.y;
            r[4 * q + 2] = v.z; r[4 * q + 3] = v.w;
        }

        float acc[OPT];
        #pragma unroll
        for (int m = 0; m < OPT; m++) {
            float a = b;
            #pragma unroll
            for (int k = 0; k < KSZ; k++)
                a = fmaf(wr[k], r[m + 1 + k], a);
            acc[m] = a;
        }

        float4 o; o.x = acc[0]; o.y = acc[1]; o.z = acc[2]; o.w = acc[3];
        *reinterpret_cast<float4*>(orow + base) = o;
    }
}

extern "C" void kernel_launch(void* const* d_in, const int* in_sizes, int n_in,
                              void* d_out, int out_size)
{
    const float* x    = (const float*)d_in[0];
    const float* w    = (const float*)d_in[1];
    const float* bias = (const float*)d_in[2];
    float* out        = (float*)d_out;

    const int rows   = 4 * DIM;                        // 8192
    const int blocks = rows * HALVES_PER_ROW;          // 16384
    causal_conv1d_kernel<<<blocks, BLOCK>>>(x, w, bias, out);
}

// round 6
// speedup vs baseline: 1.5596x; 1.1621x over previous
#include <cuda_runtime.h>
#include <cstdint>

// CausalConv1d: x (4, 2048, 8192) f32, depthwise weight (2048, 1, 16), bias (2048)
// out[n,c,l] = sum_{k=0..15} x[n,c,l-15+k] * w[c,0,k] + bias[c]   (zero-pad left)
//
// TMA-prefetch design: one block per row. tid 0 issues 8 cp.async.bulk copies
// (one per 1024-float tile, each with a 16-float left halo) into 8 smem stages
// up front; per-stage mbarrier (complete_tx) signals readiness. Consumers read
// 20-float windows with 5 conflict-free LDS.128 and store via STG.128. The
// whole row's DRAM traffic is in flight immediately -> latency fully hidden.

#define DIM    2048
#define LEN    8192
#define KSZ    16
#define BLOCK  256
#define OPT    4
#define TILE   (BLOCK * OPT)      // 1024
#define NST    (LEN / TILE)       // 8 stages
#define STAGEF (TILE + KSZ)       // 1040 floats per stage
#define STAGEB (STAGEF * 4)       // 4160 bytes

__device__ __forceinline__ uint32_t smem_u32(const void* p) {
    return (uint32_t)__cvta_generic_to_shared(p);
}

__device__ __forceinline__ void mbar_init(uint32_t mbar, uint32_t count) {
    asm volatile("mbarrier.init.shared.b64 [%0], %1;" :: "r"(mbar), "r"(count) : "memory");
}

__device__ __forceinline__ void mbar_expect_tx(uint32_t mbar, uint32_t bytes) {
    asm volatile("mbarrier.arrive.expect_tx.shared.b64 _, [%0], %1;"
                 :: "r"(mbar), "r"(bytes) : "memory");
}

__device__ __forceinline__ void bulk_g2s(uint32_t dst, const void* src,
                                         uint32_t bytes, uint32_t mbar) {
    asm volatile(
        "cp.async.bulk.shared::cta.global.mbarrier::complete_tx::bytes [%0], [%1], %2, [%3];"
        :: "r"(dst), "l"(src), "r"(bytes), "r"(mbar) : "memory");
}

__device__ __forceinline__ void mbar_wait_parity0(uint32_t mbar) {
    uint32_t done;
    asm volatile(
        "{\n\t.reg .pred p;\n\t"
        "mbarrier.try_wait.parity.acquire.cta.shared::cta.b64 p, [%1], 0;\n\t"
        "selp.b32 %0, 1, 0, p;\n\t}"
        : "=r"(done) : "r"(mbar) : "memory");
    if (!done) {
        asm volatile(
            "{\n\t.reg .pred P1;\n\t"
            "WAIT_LOOP_%=:\n\t"
            "mbarrier.try_wait.parity.acquire.cta.shared::cta.b64 P1, [%0], 0, 0x989680;\n\t"
            "@P1 bra.uni WAIT_DONE_%=;\n\t"
            "bra.uni WAIT_LOOP_%=;\n\t"
            "WAIT_DONE_%=:\n\t}"
            :: "r"(mbar) : "memory");
    }
}

__global__ __launch_bounds__(BLOCK, 4) void causal_conv1d_kernel(
    const float* __restrict__ x,
    const float* __restrict__ w,
    const float* __restrict__ bias,
    float* __restrict__ out)
{
    __shared__ alignas(128) float stage[NST][STAGEF];
    __shared__ alignas(8)   unsigned long long mbar[NST];

    const int tid = threadIdx.x;
    const int row = blockIdx.x;
    const int ch  = row & (DIM - 1);             // row = n*DIM + c

    const float* __restrict__ xrow = x   + (size_t)row * LEN;
    float*       __restrict__ orow = out + (size_t)row * LEN;

    // ---- init barriers + zero the 16-float left pad of stage 0 ----
    if (tid < NST) mbar_init(smem_u32(&mbar[tid]), 1);
    if (tid < KSZ / 4) {
        float4 z = make_float4(0.f, 0.f, 0.f, 0.f);
        *reinterpret_cast<float4*>(&stage[0][4 * tid]) = z;
    }
    __syncthreads();

    // ---- producer: prefetch all 8 stages immediately (tid 0) ----
    if (tid == 0) {
        asm volatile("fence.proxy.async.shared::cta;" ::: "memory");
        // stage 0: data starts at offset 16 (halo is the zero pad)
        mbar_expect_tx(smem_u32(&mbar[0]), TILE * 4);
        bulk_g2s(smem_u32(&stage[0][KSZ]), xrow, TILE * 4, smem_u32(&mbar[0]));
        #pragma unroll
        for (int s = 1; s < NST; s++) {
            mbar_expect_tx(smem_u32(&mbar[s]), STAGEB);
            bulk_g2s(smem_u32(&stage[s][0]), xrow + s * TILE - KSZ,
                     STAGEB, smem_u32(&mbar[s]));
        }
    }

    // ---- weights + bias (warp-uniform, overlaps TMA) ----
    float wr[KSZ];
    const float4* w4 = reinterpret_cast<const float4*>(w + ch * KSZ);
    #pragma unroll
    for (int q = 0; q < 4; q++) {
        float4 t = w4[q];
        wr[4 * q + 0] = t.x; wr[4 * q + 1] = t.y;
        wr[4 * q + 2] = t.z; wr[4 * q + 3] = t.w;
    }
    const float b = bias[ch];

    // ---- consume stage by stage ----
    #pragma unroll
    for (int s = 0; s < NST; s++) {
        mbar_wait_parity0(smem_u32(&mbar[s]));

        // window r[i] = xrow[s*TILE - 16 + 4*tid + i] = stage[s][4*tid + i]
        float r[OPT + KSZ];
        const float4* sp = reinterpret_cast<const float4*>(&stage[s][4 * tid]);
        #pragma unroll
        for (int q = 0; q < 5; q++) {
            float4 v = sp[q];
            r[4 * q + 0] = v.x; r[4 * q + 1] = v.y;
            r[4 * q + 2] = v.z; r[4 * q + 3] = v.w;
        }

        float acc[OPT];
        #pragma unroll
        for (int m = 0; m < OPT; m++) {
            float a = b;
            #pragma unroll
            for (int k = 0; k < KSZ; k++)
                a = fmaf(wr[k], r[m + 1 + k], a);
            acc[m] = a;
        }

        float4 o; o.x = acc[0]; o.y = acc[1]; o.z = acc[2]; o.w = acc[3];
        *reinterpret_cast<float4*>(orow + s * TILE + 4 * tid) = o;
    }
}

extern "C" void kernel_launch(void* const* d_in, const int* in_sizes, int n_in,
                              void* d_out, int out_size)
{
    const float* x    = (const float*)d_in[0];
    const float* w    = (const float*)d_in[1];
    const float* bias = (const float*)d_in[2];
    float* out        = (float*)d_out;

    const int blocks = 4 * DIM;                  // 8192 rows
    causal_conv1d_kernel<<<blocks, BLOCK>>>(x, w, bias, out);
}